// round 15
// baseline (speedup 1.0000x reference)
#include <cuda_runtime.h>
#include <cuda_bf16.h>
#include <cstdint>

#define DIN 80
#define DOUT 160
#define NROWS 262144
#define EPSV 1e-5f
#define P1_BLOCKS 256

// ---- device scratch --------------------------------------------------------
__device__ float gSpart[3 * P1_BLOCKS * DIN];
__device__ float gS[3 * DIN];
__device__ float gCpart[(size_t)3 * P1_BLOCKS * DIN * DIN];
__device__ float gC[3 * DIN * DIN];
__device__ __align__(16) __nv_bfloat16 gMbf[3][2][80 * 88]; // hi/lo, pitch 88
__device__ float gU[3 * DIN];
__device__ float gV[3 * DIN];
__device__ float gCc[3];

struct Params { const float *W[3], *b[3], *g[3], *be[3]; };

__device__ __forceinline__ uint32_t smem_u32(const void* p) {
    uint32_t a;
    asm("{ .reg .u64 t; cvta.to.shared.u64 t, %1; cvt.u32.u64 %0, t; }"
        : "=r"(a) : "l"(p));
    return a;
}
__device__ __forceinline__ void ldsm4(uint32_t& a0, uint32_t& a1, uint32_t& a2,
                                      uint32_t& a3, uint32_t addr) {
    asm volatile("ldmatrix.sync.aligned.m8n8.x4.shared.b16 {%0,%1,%2,%3}, [%4];"
                 : "=r"(a0), "=r"(a1), "=r"(a2), "=r"(a3) : "r"(addr));
}
__device__ __forceinline__ void ldsm2(uint32_t& b0, uint32_t& b1, uint32_t addr) {
    asm volatile("ldmatrix.sync.aligned.m8n8.x2.shared.b16 {%0,%1}, [%2];"
                 : "=r"(b0), "=r"(b1) : "r"(addr));
}
__device__ __forceinline__ void mma16816(float* d, uint32_t a0, uint32_t a1,
                                         uint32_t a2, uint32_t a3,
                                         uint32_t b0, uint32_t b1) {
    asm volatile("mma.sync.aligned.m16n8k16.row.col.f32.bf16.bf16.f32 "
                 "{%0,%1,%2,%3}, {%4,%5,%6,%7}, {%8,%9}, {%0,%1,%2,%3};"
                 : "+f"(d[0]), "+f"(d[1]), "+f"(d[2]), "+f"(d[3])
                 : "r"(a0), "r"(a1), "r"(a2), "r"(a3), "r"(b0), "r"(b1));
}
__device__ __forceinline__ uint32_t bfpack(float a, float b) {
    __nv_bfloat162 t(__float2bfloat16(a), __float2bfloat16(b));
    return *(uint32_t*)&t;
}
__device__ __forceinline__ float2 rd2(const char* hi, const char* lo, int off) {
    __nv_bfloat162 h = *(const __nv_bfloat162*)(hi + off);
    __nv_bfloat162 l = *(const __nv_bfloat162*)(lo + off);
    return make_float2(__bfloat162float(h.x) + __bfloat162float(l.x),
                       __bfloat162float(h.y) + __bfloat162float(l.y));
}

// ---------------------------------------------------------------------------
// K1: X^T X per stream via mma.sync split-2 bf16. 320 thr = 10 warps,
// warp (wm = w>>1, wn = w&1) owns C rows 16wm..+15, cols 40wn..+39.
// XT hi/lo tiles [80 q][128 r] bf16, pitch 272 B (ldmatrix conflict-free).
// Column sums accumulated exactly in fp32 during conversion (fixed q/thread).
// ---------------------------------------------------------------------------
#define XTP 272                       // bytes per XT row (136 bf16)
#define P1T 8                         // tiles per block (8*128 = 1024 rows)

__global__ __launch_bounds__(320)
void k_xtx(const float* __restrict__ X0, const float* __restrict__ X1,
           const float* __restrict__ X2)
{
    __shared__ __align__(16) char XTh[80 * XTP];
    __shared__ __align__(16) char XTl[80 * XTP];
    __shared__ float psC[16 * 80];

    const int s = blockIdx.y;
    const float* X = (s == 0) ? X0 : (s == 1) ? X1 : X2;
    const int tid = threadIdx.x, wid = tid >> 5, lane = tid & 31;
    const int wm = wid >> 1, wn = wid & 1;
    const uint32_t sh = smem_u32(XTh), sl = smem_u32(XTl);

    const int aln = lane & 15, akoff = (lane < 16) ? 0 : 16;
    const int bln = lane & 7,  bkoff = (lane & 8) ? 16 : 0;
    const int g = lane >> 2, tq = lane & 3;

    float d[5][4];
#pragma unroll
    for (int n = 0; n < 5; ++n)
#pragma unroll
        for (int i = 0; i < 4; ++i) d[n][i] = 0.f;
    float cs4[4] = {0.f, 0.f, 0.f, 0.f};

    const long long rowbase = (long long)blockIdx.x * (P1T * 128);
    const int myk4 = tid % 20;        // fixed column group per thread

    for (int t = 0; t < P1T; ++t) {
        const float4* src4 = (const float4*)(X + (rowbase + (long long)t * 128) * DIN);
        for (int i4 = tid; i4 < 128 * 20; i4 += 320) {
            int r = i4 / 20, q0 = 4 * (i4 % 20);
            float4 v = src4[i4];
            float vv[4] = {v.x, v.y, v.z, v.w};
#pragma unroll
            for (int j = 0; j < 4; ++j) {
                __nv_bfloat16 h = __float2bfloat16(vv[j]);
                *(__nv_bfloat16*)(XTh + (q0 + j) * XTP + 2 * r) = h;
                *(__nv_bfloat16*)(XTl + (q0 + j) * XTP + 2 * r) =
                    __float2bfloat16(vv[j] - __bfloat162float(h));
                cs4[j] += vv[j];
            }
        }
        __syncthreads();

        const uint32_t tA[3] = {sh, sh, sl};
        const uint32_t tB[3] = {sh, sl, sh};
#pragma unroll
        for (int term = 0; term < 3; ++term) {
            uint32_t abase = tA[term] + (16 * wm + aln) * XTP + akoff;
            uint32_t bbase = tB[term] + (40 * wn + bln) * XTP + bkoff;
#pragma unroll
            for (int ks = 0; ks < 8; ++ks) {
                uint32_t a0, a1, a2, a3;
                ldsm4(a0, a1, a2, a3, abase + ks * 32);
#pragma unroll
                for (int n = 0; n < 5; ++n) {
                    uint32_t b0, b1;
                    ldsm2(b0, b1, bbase + n * 8 * XTP + ks * 32);
                    mma16816(d[n], a0, a1, a2, a3, b0, b1);
                }
            }
        }
        __syncthreads();
    }

    // partial C store (full 80x80)
    float* dst = gCpart + (size_t)(s * P1_BLOCKS + blockIdx.x) * (DIN * DIN);
    const int r0 = 16 * wm + g, r1 = r0 + 8;
#pragma unroll
    for (int n = 0; n < 5; ++n) {
        int c = 40 * wn + 8 * n + 2 * tq;
        dst[r0 * DIN + c]     = d[n][0];
        dst[r0 * DIN + c + 1] = d[n][1];
        dst[r1 * DIN + c]     = d[n][2];
        dst[r1 * DIN + c + 1] = d[n][3];
    }
    // column sums: thread owns cols 4*myk4..+3 for rows tid/20 (mod 16)
#pragma unroll
    for (int j = 0; j < 4; ++j) psC[(tid / 20) * 80 + 4 * myk4 + j] = cs4[j];
    __syncthreads();
    if (tid < DIN) {
        float acc = 0.f;
#pragma unroll
        for (int gg = 0; gg < 16; ++gg) acc += psC[gg * 80 + tid];
        gSpart[(s * P1_BLOCKS + blockIdx.x) * DIN + tid] = acc;
    }
}

// ---------------------------------------------------------------------------
// K2: reduce partials (full matrix now — no mirror).
// ---------------------------------------------------------------------------
__global__ void k_reduceC()
{
    int e = blockIdx.x * blockDim.x + threadIdx.x;
    if (e < 3 * DIN * DIN) {
        int s = e / (DIN * DIN), rem = e - s * DIN * DIN;
        const float* src = gCpart + (size_t)s * P1_BLOCKS * (DIN * DIN) + rem;
        float acc = 0.f;
#pragma unroll 8
        for (int b = 0; b < P1_BLOCKS; ++b) acc += src[(size_t)b * (DIN * DIN)];
        gC[e] = acc;
    } else if (e < 3 * DIN * DIN + 3 * DIN) {
        int h = e - 3 * DIN * DIN, s = h / DIN, k = h - s * DIN;
        float acc = 0.f;
#pragma unroll 8
        for (int b = 0; b < P1_BLOCKS; ++b) acc += gSpart[(s * P1_BLOCKS + b) * DIN + k];
        gS[s * DIN + k] = acc;
    }
}

// ---------------------------------------------------------------------------
// K3: fused stats + build M (split-2 bf16, [p][q] pitch 88), u, v, c.
// ---------------------------------------------------------------------------
#define WP 84
#define TPP (DOUT + 8)
#define PREP_SMEM ((2*DOUT*WP + DIN*DIN + 16*TPP + DOUT + DIN + 2*DOUT) * 4)

__global__ __launch_bounds__(256)
void k_prep(Params P, float invN)
{
    extern __shared__ __align__(16) float sp[];
    float* WsA = sp;
    float* WsB = WsA + DOUT * WP;
    float* Cs  = WsB + DOUT * WP;
    float* Tp  = Cs + DIN * DIN;
    float* alphas = Tp + 16 * TPP;
    float* xbs = alphas + DOUT;
    float* dA  = xbs + DIN;
    float* dB  = dA + DOUT;

    const int s = blockIdx.x;
    const int a_idx = (s == 2) ? 1 : 0;
    const int b_idx = (s == 0) ? 1 : 2;
    const int tid = threadIdx.x, tj = tid & 15, tk = tid >> 4;

    for (int ph = 0; ph < 2; ++ph) {
        const int t = ph ? b_idx : a_idx;
        float* Ws = ph ? WsB : WsA;
        float* dd = ph ? dB : dA;
        const float4* Wg4 = (const float4*)P.W[t];
        for (int i4 = tid; i4 < DOUT * 20; i4 += 256) {
            int j = i4 / 20, k4 = i4 - j * 20;
            *(float4*)&Ws[j * WP + 4 * k4] = Wg4[i4];
        }
        const float4* Cg4 = (const float4*)&gC[t * DIN * DIN];
        for (int i4 = tid; i4 < (DIN * DIN) / 4; i4 += 256) ((float4*)Cs)[i4] = Cg4[i4];
        if (tid < DIN) xbs[tid] = gS[t * DIN + tid] * invN;
        __syncthreads();

        float acc[10][5];
#pragma unroll
        for (int aa = 0; aa < 10; ++aa)
#pragma unroll
            for (int bb = 0; bb < 5; ++bb) acc[aa][bb] = 0.f;
        for (int m = 0; m < DIN; ++m) {
            float wv[10], cv[5];
#pragma unroll
            for (int aa = 0; aa < 10; ++aa) wv[aa] = Ws[(tj + 16 * aa) * WP + m];
#pragma unroll
            for (int bb = 0; bb < 5; ++bb) cv[bb] = Cs[m * DIN + tk + 16 * bb];
#pragma unroll
            for (int aa = 0; aa < 10; ++aa)
#pragma unroll
                for (int bb = 0; bb < 5; ++bb) acc[aa][bb] += wv[aa] * cv[bb];
        }
#pragma unroll
        for (int aa = 0; aa < 10; ++aa) {
            float ps = 0.f;
#pragma unroll
            for (int bb = 0; bb < 5; ++bb)
                ps += acc[aa][bb] * Ws[(tj + 16 * aa) * WP + tk + 16 * bb];
            Tp[tk * TPP + tj + 16 * aa] = ps;
        }
        __syncthreads();
        if (tid < DOUT) {
            float q = 0.f;
#pragma unroll
            for (int g = 0; g < 16; ++g) q += Tp[g * TPP + tid];
            float wx = 0.f;
#pragma unroll 8
            for (int m = 0; m < DIN; ++m) wx += Ws[tid * WP + m] * xbs[m];
            float bj = P.b[t][tid], mu = wx + bj;
            float var = q * invN - wx * wx;
            float alpha = P.g[t][tid] * rsqrtf(var + EPSV);
            dd[tid] = alpha * bj + (P.be[t][tid] - mu * alpha);
            alphas[tid] = alpha;
        }
        __syncthreads();
        for (int i = tid; i < DOUT * DIN; i += 256) {
            int j = i / DIN, m = i - j * DIN;
            Ws[j * WP + m] *= alphas[j];
        }
        __syncthreads();
    }

    float macc[5][5];
#pragma unroll
    for (int aa = 0; aa < 5; ++aa)
#pragma unroll
        for (int bb = 0; bb < 5; ++bb) macc[aa][bb] = 0.f;
    for (int j = 0; j < DOUT; ++j) {
        float av[5], bv[5];
#pragma unroll
        for (int aa = 0; aa < 5; ++aa) av[aa] = WsA[j * WP + tj + 16 * aa];
#pragma unroll
        for (int bb = 0; bb < 5; ++bb) bv[bb] = WsB[j * WP + tk + 16 * bb];
#pragma unroll
        for (int aa = 0; aa < 5; ++aa)
#pragma unroll
            for (int bb = 0; bb < 5; ++bb) macc[aa][bb] += av[aa] * bv[bb];
    }
    __nv_bfloat16* mh = gMbf[s][0];
    __nv_bfloat16* ml = gMbf[s][1];
#pragma unroll
    for (int aa = 0; aa < 5; ++aa)
#pragma unroll
        for (int bb = 0; bb < 5; ++bb) {
            int p = tj + 16 * aa, q = tk + 16 * bb;
            float m = macc[aa][bb];
            __nv_bfloat16 h = __float2bfloat16(m);
            mh[p * 88 + q] = h;
            ml[p * 88 + q] = __float2bfloat16(m - __bfloat162float(h));
        }
    if (tid < DIN) {
        float u = 0.f;
        for (int j = 0; j < DOUT; ++j) u += WsA[j * WP + tid] * dB[j];
        gU[s * DIN + tid] = u;
    } else if (tid < 2 * DIN) {
        int q = tid - DIN;
        float v = 0.f;
        for (int j = 0; j < DOUT; ++j) v += dA[j] * WsB[j * WP + q];
        gV[s * DIN + q] = v;
    } else if (tid == 2 * DIN) {
        float c = 0.f;
        for (int j = 0; j < DOUT; ++j) c += dA[j] * dB[j];
        gCc[s] = c;
    }
}

// ---------------------------------------------------------------------------
// K4: mma.sync main pass. 64 rows/block, 256 thr = 8 warps (wm 0..3, wn 0..1).
// smem ~98 KB -> 2 blocks/SM (16 warps/SM vs 8 in R14).
// ---------------------------------------------------------------------------
#define XPITCH 176
#define XB(t, h) (((t) * 2 + (h)) * 11264)       // 64*176 each
#define O_M   67584                               // [2][80][88] bf16 = 28160
#define O_US  95744
#define O_VS  96704
#define O_CC  97664
#define O_SIM 97680                               // [2][3][64] f32 = 1536
#define O_PSM 99216                               // [3][64] f32 = 768
#define KMAIN_SMEM 99984

__global__ __launch_bounds__(256, 2)
void k_main(const float* __restrict__ X0, const float* __restrict__ X1,
            const float* __restrict__ X2, float* __restrict__ out)
{
    extern __shared__ __align__(16) char smc[];
    float* us   = (float*)(smc + O_US);
    float* vs   = (float*)(smc + O_VS);
    float* ccs  = (float*)(smc + O_CC);
    float* simw = (float*)(smc + O_SIM);
    float* psm  = (float*)(smc + O_PSM);
    const uint32_t sb = smem_u32(smc);
    const int tid = threadIdx.x, wid = tid >> 5, lane = tid & 31;
    const int wm = wid >> 1, wn = wid & 1;
    const long long base = (long long)blockIdx.x * 64;

    // phase A: convert all 3 streams to bf16 hi/lo tiles (64 rows)
    const float* Xp[3] = {X0, X1, X2};
    for (int t = 0; t < 3; ++t) {
        const float4* src4 = (const float4*)(Xp[t] + base * DIN);
        char* hi = smc + XB(t, 0);
        char* lo = smc + XB(t, 1);
        for (int i4 = tid; i4 < 64 * 20; i4 += 256) {
            int r = i4 / 20, q0 = 4 * (i4 - r * 20);
            float4 v = src4[i4];
            __nv_bfloat16 h0 = __float2bfloat16(v.x), h1 = __float2bfloat16(v.y);
            __nv_bfloat16 h2 = __float2bfloat16(v.z), h3 = __float2bfloat16(v.w);
            int o = r * XPITCH + q0 * 2;
            __nv_bfloat162 p01(h0, h1), p23(h2, h3);
            *(uint32_t*)(hi + o)     = *(uint32_t*)&p01;
            *(uint32_t*)(hi + o + 4) = *(uint32_t*)&p23;
            *(uint32_t*)(lo + o)     = bfpack(v.x - __bfloat162float(h0),
                                              v.y - __bfloat162float(h1));
            *(uint32_t*)(lo + o + 4) = bfpack(v.z - __bfloat162float(h2),
                                              v.w - __bfloat162float(h3));
        }
    }
    if (tid < 3 * DIN) { us[tid] = gU[tid]; vs[tid] = gV[tid]; }
    if (tid < 3)       ccs[tid] = gCc[tid];
    __syncthreads();

    const int g = lane >> 2, tq = lane & 3;
    const int aln = lane & 15, akoff = (lane < 16) ? 0 : 16;
    const int bln = lane & 7,  bkoff = (lane & 8) ? 16 : 0;

    for (int s = 0; s < 3; ++s) {
        const int aS = (s == 2) ? 1 : 0;   // x_a stream
        const int bS = (s == 0) ? 1 : 2;   // x_b stream

        const float4* mg = (const float4*)gMbf[s][0];
        for (int i = tid; i < 1760; i += 256) ((float4*)(smc + O_M))[i] = mg[i];
        __syncthreads();

        float d[5][4];
#pragma unroll
        for (int n = 0; n < 5; ++n)
#pragma unroll
            for (int i = 0; i < 4; ++i) d[n][i] = 0.f;

        const uint32_t tA[3] = {sb + XB(bS, 0), sb + XB(bS, 0), sb + XB(bS, 1)};
        const uint32_t tB[3] = {sb + O_M, sb + O_M + 14080, sb + O_M};
#pragma unroll
        for (int term = 0; term < 3; ++term) {
            uint32_t abase = tA[term] + (16 * wm + aln) * XPITCH + akoff;
            uint32_t bbase = tB[term] + (40 * wn + bln) * XPITCH + bkoff;
#pragma unroll
            for (int ks = 0; ks < 5; ++ks) {
                uint32_t a0, a1, a2, a3;
                ldsm4(a0, a1, a2, a3, abase + ks * 32);
#pragma unroll
                for (int n = 0; n < 5; ++n) {
                    uint32_t b0, b1;
                    ldsm2(b0, b1, bbase + n * 8 * XPITCH + ks * 32);
                    mma16816(d[n], a0, a1, a2, a3, b0, b1);
                }
            }
        }

        // fragment epilogue over this warp's p-range (40wn..40wn+39)
        const char* ah = smc + XB(aS, 0);
        const char* al = smc + XB(aS, 1);
        const char* bh = smc + XB(bS, 0);
        const char* bl = smc + XB(bS, 1);
        const int r0 = 16 * wm + g, r1 = r0 + 8;
        float s0 = 0.f, s1 = 0.f;
#pragma unroll
        for (int n = 0; n < 5; ++n) {
            int p0 = 40 * wn + 8 * n + 2 * tq;
            float2 uu = *(const float2*)&us[s * DIN + p0];
            float2 vv = *(const float2*)&vs[s * DIN + p0];
            float2 xa0 = rd2(ah, al, r0 * XPITCH + p0 * 2);
            float2 xa1 = rd2(ah, al, r1 * XPITCH + p0 * 2);
            float2 xb0 = rd2(bh, bl, r0 * XPITCH + p0 * 2);
            float2 xb1 = rd2(bh, bl, r1 * XPITCH + p0 * 2);
            s0 += (d[n][0] + uu.x) * xa0.x + (d[n][1] + uu.y) * xa0.y
                + vv.x * xb0.x + vv.y * xb0.y;
            s1 += (d[n][2] + uu.x) * xa1.x + (d[n][3] + uu.y) * xa1.y
                + vv.x * xb1.x + vv.y * xb1.y;
        }
        s0 += __shfl_xor_sync(0xffffffff, s0, 1);
        s0 += __shfl_xor_sync(0xffffffff, s0, 2);
        s1 += __shfl_xor_sync(0xffffffff, s1, 1);
        s1 += __shfl_xor_sync(0xffffffff, s1, 2);
        if (tq == 0) {
            simw[(wn * 3 + s) * 64 + r0] = s0;
            simw[(wn * 3 + s) * 64 + r1] = s1;
        }
        __syncthreads();   // sims written; M smem free for next pair
    }

    // softmax per row (combine wn partials)
    if (tid < 64) {
        float s0 = simw[0 * 64 + tid] + simw[(3 + 0) * 64 + tid] + ccs[0];
        float s1 = simw[1 * 64 + tid] + simw[(3 + 1) * 64 + tid] + ccs[1];
        float s2 = simw[2 * 64 + tid] + simw[(3 + 2) * 64 + tid] + ccs[2];
        float m = fmaxf(s0, fmaxf(s1, s2));
        float e0 = __expf(s0 - m), e1 = __expf(s1 - m), e2 = __expf(s2 - m);
        float inv = 1.f / (e0 + e1 + e2);
        psm[tid] = e0 * inv;
        psm[64 + tid] = e1 * inv;
        psm[128 + tid] = e2 * inv;
    }
    __syncthreads();

    // blend (coalesced): out = p0*left + p1*right + p2*sub
    const float4* s4 = (const float4*)(X0 + base * DIN);
    const float4* l4 = (const float4*)(X1 + base * DIN);
    const float4* r4 = (const float4*)(X2 + base * DIN);
    float4* d4 = (float4*)(out + base * DIN);
    for (int i4 = tid; i4 < 64 * 20; i4 += 256) {
        int r = i4 / 20;
        float p0 = psm[r], p1 = psm[64 + r], p2 = psm[128 + r];
        float4 a = s4[i4], b = l4[i4], c = r4[i4], o;
        o.x = p0 * b.x + p1 * c.x + p2 * a.x;
        o.y = p0 * b.y + p1 * c.y + p2 * a.y;
        o.z = p0 * b.z + p1 * c.z + p2 * a.z;
        o.w = p0 * b.w + p1 * c.w + p2 * a.w;
        d4[i4] = o;
    }
}

// ---------------------------------------------------------------------------
extern "C" void kernel_launch(void* const* d_in, const int* in_sizes, int n_in,
                              void* d_out, int out_size)
{
    const float* sub   = (const float*)d_in[0];
    const float* left  = (const float*)d_in[1];
    const float* right = (const float*)d_in[2];
    Params P;
    for (int s = 0; s < 3; ++s) {
        P.W[s]  = (const float*)d_in[3 + 4 * s + 0];
        P.b[s]  = (const float*)d_in[3 + 4 * s + 1];
        P.g[s]  = (const float*)d_in[3 + 4 * s + 2];
        P.be[s] = (const float*)d_in[3 + 4 * s + 3];
    }
    cudaFuncSetAttribute(k_prep, cudaFuncAttributeMaxDynamicSharedMemorySize, PREP_SMEM);
    cudaFuncSetAttribute(k_main, cudaFuncAttributeMaxDynamicSharedMemorySize, KMAIN_SMEM);

    k_xtx<<<dim3(P1_BLOCKS, 3), 320>>>(sub, left, right);
    k_reduceC<<<(3 * DIN * DIN + 3 * DIN + 255) / 256, 256>>>();
    k_prep<<<3, 256, PREP_SMEM>>>(P, 1.0f / (float)NROWS);
    k_main<<<NROWS / 64, 256, KMAIN_SMEM>>>(sub, left, right, (float*)d_out);
}

// round 16
// speedup vs baseline: 1.2069x; 1.2069x over previous
#include <cuda_runtime.h>
#include <cuda_bf16.h>
#include <cstdint>

#define DIN 80
#define DOUT 160
#define NROWS 262144
#define EPSV 1e-5f
#define P1_BLOCKS 256

// ---- device scratch --------------------------------------------------------
__device__ float gSpart[3 * P1_BLOCKS * DIN];
__device__ float gS[3 * DIN];
__device__ float gCpart[(size_t)3 * P1_BLOCKS * DIN * DIN];
__device__ float gC[3 * DIN * DIN];
__device__ __align__(16) __nv_bfloat16 gMbf[3][2][80 * 88]; // hi/lo, pitch 88
__device__ float gU[3 * DIN];
__device__ float gV[3 * DIN];
__device__ float gCc[3];

struct Params { const float *W[3], *b[3], *g[3], *be[3]; };

__device__ __forceinline__ uint32_t smem_u32(const void* p) {
    uint32_t a;
    asm("{ .reg .u64 t; cvta.to.shared.u64 t, %1; cvt.u32.u64 %0, t; }"
        : "=r"(a) : "l"(p));
    return a;
}
__device__ __forceinline__ void ldsm4(uint32_t& a0, uint32_t& a1, uint32_t& a2,
                                      uint32_t& a3, uint32_t addr) {
    asm volatile("ldmatrix.sync.aligned.m8n8.x4.shared.b16 {%0,%1,%2,%3}, [%4];"
                 : "=r"(a0), "=r"(a1), "=r"(a2), "=r"(a3) : "r"(addr));
}
__device__ __forceinline__ void ldsm2(uint32_t& b0, uint32_t& b1, uint32_t addr) {
    asm volatile("ldmatrix.sync.aligned.m8n8.x2.shared.b16 {%0,%1}, [%2];"
                 : "=r"(b0), "=r"(b1) : "r"(addr));
}
__device__ __forceinline__ void ldsm4t(uint32_t& a0, uint32_t& a1, uint32_t& a2,
                                       uint32_t& a3, uint32_t addr) {
    asm volatile("ldmatrix.sync.aligned.m8n8.x4.trans.shared.b16 {%0,%1,%2,%3}, [%4];"
                 : "=r"(a0), "=r"(a1), "=r"(a2), "=r"(a3) : "r"(addr));
}
__device__ __forceinline__ void ldsm2t(uint32_t& b0, uint32_t& b1, uint32_t addr) {
    asm volatile("ldmatrix.sync.aligned.m8n8.x2.trans.shared.b16 {%0,%1}, [%2];"
                 : "=r"(b0), "=r"(b1) : "r"(addr));
}
__device__ __forceinline__ void mma16816(float* d, uint32_t a0, uint32_t a1,
                                         uint32_t a2, uint32_t a3,
                                         uint32_t b0, uint32_t b1) {
    asm volatile("mma.sync.aligned.m16n8k16.row.col.f32.bf16.bf16.f32 "
                 "{%0,%1,%2,%3}, {%4,%5,%6,%7}, {%8,%9}, {%0,%1,%2,%3};"
                 : "+f"(d[0]), "+f"(d[1]), "+f"(d[2]), "+f"(d[3])
                 : "r"(a0), "r"(a1), "r"(a2), "r"(a3), "r"(b0), "r"(b1));
}
__device__ __forceinline__ uint32_t bfpack(float a, float b) {
    __nv_bfloat162 t(__float2bfloat16(a), __float2bfloat16(b));
    return *(uint32_t*)&t;
}
__device__ __forceinline__ float2 rd2(const char* hi, const char* lo, int off) {
    __nv_bfloat162 h = *(const __nv_bfloat162*)(hi + off);
    __nv_bfloat162 l = *(const __nv_bfloat162*)(lo + off);
    return make_float2(__bfloat162float(h.x) + __bfloat162float(l.x),
                       __bfloat162float(h.y) + __bfloat162float(l.y));
}

// ---------------------------------------------------------------------------
// K1: X^T X per stream via mma.sync split-2 bf16 with ldmatrix.trans.
// X tiles stored ROW-MAJOR bf16 hi/lo ([128 r][80 q], pitch 176 B) — the
// conversion is coalesced/vectorized (the R15 transposed-store version had
// ~10-way STS conflicts and regressed). A and B fragments of X^T come from
// .trans loads. 320 thr = 10 warps; warp (wm=w>>1, wn=w&1) owns C rows
// 16wm..+15, cols 40wn..+39. Column sums exact fp32 during conversion.
// ---------------------------------------------------------------------------
#define XP1 176
#define P1T 8                         // 8 * 128 = 1024 rows per block

__global__ __launch_bounds__(320)
void k_xtx(const float* __restrict__ X0, const float* __restrict__ X1,
           const float* __restrict__ X2)
{
    __shared__ __align__(16) char XH[128 * XP1];
    __shared__ __align__(16) char XL[128 * XP1];
    __shared__ float psC[16 * 80];

    const int s = blockIdx.y;
    const float* X = (s == 0) ? X0 : (s == 1) ? X1 : X2;
    const int tid = threadIdx.x, wid = tid >> 5, lane = tid & 31;
    const int wm = wid >> 1, wn = wid & 1;
    const uint32_t sh = smem_u32(XH), sl = smem_u32(XL);

    // .trans address lanes (derived from the R14-validated non-trans mapping)
    const int arow = (lane & 7) + ((lane & 16) ? 8 : 0);  // A: x4.trans
    const int aoff = (lane & 8) ? 16 : 0;
    const int brow = (lane & 7) + ((lane & 8) ? 8 : 0);   // B: x2.trans
    const int g = lane >> 2, tq = lane & 3;

    float d[5][4];
#pragma unroll
    for (int n = 0; n < 5; ++n)
#pragma unroll
        for (int i = 0; i < 4; ++i) d[n][i] = 0.f;
    float cs4[4] = {0.f, 0.f, 0.f, 0.f};

    const long long rowbase = (long long)blockIdx.x * (P1T * 128);

    for (int t = 0; t < P1T; ++t) {
        const float4* src4 = (const float4*)(X + (rowbase + (long long)t * 128) * DIN);
        for (int i4 = tid; i4 < 128 * 20; i4 += 320) {
            int r = i4 / 20, q0 = 4 * (i4 % 20);
            float4 v = src4[i4];
            __nv_bfloat16 h0 = __float2bfloat16(v.x), h1 = __float2bfloat16(v.y);
            __nv_bfloat16 h2 = __float2bfloat16(v.z), h3 = __float2bfloat16(v.w);
            int o = r * XP1 + q0 * 2;
            __nv_bfloat162 p01(h0, h1), p23(h2, h3);
            *(uint32_t*)(XH + o)     = *(uint32_t*)&p01;
            *(uint32_t*)(XH + o + 4) = *(uint32_t*)&p23;
            *(uint32_t*)(XL + o)     = bfpack(v.x - __bfloat162float(h0),
                                              v.y - __bfloat162float(h1));
            *(uint32_t*)(XL + o + 4) = bfpack(v.z - __bfloat162float(h2),
                                              v.w - __bfloat162float(h3));
            cs4[0] += v.x; cs4[1] += v.y; cs4[2] += v.z; cs4[3] += v.w;
        }
        __syncthreads();

        const uint32_t tA[3] = {sh, sh, sl};
        const uint32_t tB[3] = {sh, sl, sh};
#pragma unroll
        for (int term = 0; term < 3; ++term) {
            uint32_t abase = tA[term] + arow * XP1 + aoff + 32 * wm;
            uint32_t bbase = tB[term] + brow * XP1 + 80 * wn;
#pragma unroll
            for (int ks = 0; ks < 8; ++ks) {
                uint32_t a0, a1, a2, a3;
                ldsm4t(a0, a1, a2, a3, abase + ks * 16 * XP1);
#pragma unroll
                for (int n = 0; n < 5; ++n) {
                    uint32_t b0, b1;
                    ldsm2t(b0, b1, bbase + ks * 16 * XP1 + 16 * n);
                    mma16816(d[n], a0, a1, a2, a3, b0, b1);
                }
            }
        }
        __syncthreads();
    }

    // partial C store (full 80x80)
    float* dst = gCpart + (size_t)(s * P1_BLOCKS + blockIdx.x) * (DIN * DIN);
    const int r0 = 16 * wm + g, r1 = r0 + 8;
#pragma unroll
    for (int n = 0; n < 5; ++n) {
        int c = 40 * wn + 8 * n + 2 * tq;
        dst[r0 * DIN + c]     = d[n][0];
        dst[r0 * DIN + c + 1] = d[n][1];
        dst[r1 * DIN + c]     = d[n][2];
        dst[r1 * DIN + c + 1] = d[n][3];
    }
    // column sums: thread's fixed q-group = 4*(tid%20)
#pragma unroll
    for (int j = 0; j < 4; ++j) psC[(tid / 20) * 80 + 4 * (tid % 20) + j] = cs4[j];
    __syncthreads();
    if (tid < DIN) {
        float acc = 0.f;
#pragma unroll
        for (int gg = 0; gg < 16; ++gg) acc += psC[gg * 80 + tid];
        gSpart[(s * P1_BLOCKS + blockIdx.x) * DIN + tid] = acc;
    }
}

// ---------------------------------------------------------------------------
// K2: reduce partials (full matrix — no mirror).
// ---------------------------------------------------------------------------
__global__ void k_reduceC()
{
    int e = blockIdx.x * blockDim.x + threadIdx.x;
    if (e < 3 * DIN * DIN) {
        const float* src = gCpart + (size_t)(e / (DIN * DIN)) * P1_BLOCKS * (DIN * DIN)
                         + (e % (DIN * DIN));
        float acc = 0.f;
#pragma unroll 8
        for (int b = 0; b < P1_BLOCKS; ++b) acc += src[(size_t)b * (DIN * DIN)];
        gC[e] = acc;
    } else if (e < 3 * DIN * DIN + 3 * DIN) {
        int h = e - 3 * DIN * DIN, s = h / DIN, k = h - s * DIN;
        float acc = 0.f;
#pragma unroll 8
        for (int b = 0; b < P1_BLOCKS; ++b) acc += gSpart[(s * P1_BLOCKS + b) * DIN + k];
        gS[s * DIN + k] = acc;
    }
}

// ---------------------------------------------------------------------------
// K3: fused stats + build M (split-2 bf16, [p][q] pitch 88), u, v, c.
// ---------------------------------------------------------------------------
#define WP 84
#define TPP (DOUT + 8)
#define PREP_SMEM ((2*DOUT*WP + DIN*DIN + 16*TPP + DOUT + DIN + 2*DOUT) * 4)

__global__ __launch_bounds__(256)
void k_prep(Params P, float invN)
{
    extern __shared__ __align__(16) float sp[];
    float* WsA = sp;
    float* WsB = WsA + DOUT * WP;
    float* Cs  = WsB + DOUT * WP;
    float* Tp  = Cs + DIN * DIN;
    float* alphas = Tp + 16 * TPP;
    float* xbs = alphas + DOUT;
    float* dA  = xbs + DIN;
    float* dB  = dA + DOUT;

    const int s = blockIdx.x;
    const int a_idx = (s == 2) ? 1 : 0;
    const int b_idx = (s == 0) ? 1 : 2;
    const int tid = threadIdx.x, tj = tid & 15, tk = tid >> 4;

    for (int ph = 0; ph < 2; ++ph) {
        const int t = ph ? b_idx : a_idx;
        float* Ws = ph ? WsB : WsA;
        float* dd = ph ? dB : dA;
        const float4* Wg4 = (const float4*)P.W[t];
        for (int i4 = tid; i4 < DOUT * 20; i4 += 256) {
            int j = i4 / 20, k4 = i4 - j * 20;
            *(float4*)&Ws[j * WP + 4 * k4] = Wg4[i4];
        }
        const float4* Cg4 = (const float4*)&gC[t * DIN * DIN];
        for (int i4 = tid; i4 < (DIN * DIN) / 4; i4 += 256) ((float4*)Cs)[i4] = Cg4[i4];
        if (tid < DIN) xbs[tid] = gS[t * DIN + tid] * invN;
        __syncthreads();

        float acc[10][5];
#pragma unroll
        for (int aa = 0; aa < 10; ++aa)
#pragma unroll
            for (int bb = 0; bb < 5; ++bb) acc[aa][bb] = 0.f;
        for (int m = 0; m < DIN; ++m) {
            float wv[10], cv[5];
#pragma unroll
            for (int aa = 0; aa < 10; ++aa) wv[aa] = Ws[(tj + 16 * aa) * WP + m];
#pragma unroll
            for (int bb = 0; bb < 5; ++bb) cv[bb] = Cs[m * DIN + tk + 16 * bb];
#pragma unroll
            for (int aa = 0; aa < 10; ++aa)
#pragma unroll
                for (int bb = 0; bb < 5; ++bb) acc[aa][bb] += wv[aa] * cv[bb];
        }
#pragma unroll
        for (int aa = 0; aa < 10; ++aa) {
            float ps = 0.f;
#pragma unroll
            for (int bb = 0; bb < 5; ++bb)
                ps += acc[aa][bb] * Ws[(tj + 16 * aa) * WP + tk + 16 * bb];
            Tp[tk * TPP + tj + 16 * aa] = ps;
        }
        __syncthreads();
        if (tid < DOUT) {
            float q = 0.f;
#pragma unroll
            for (int g = 0; g < 16; ++g) q += Tp[g * TPP + tid];
            float wx = 0.f;
#pragma unroll 8
            for (int m = 0; m < DIN; ++m) wx += Ws[tid * WP + m] * xbs[m];
            float bj = P.b[t][tid], mu = wx + bj;
            float var = q * invN - wx * wx;
            float alpha = P.g[t][tid] * rsqrtf(var + EPSV);
            dd[tid] = alpha * bj + (P.be[t][tid] - mu * alpha);
            alphas[tid] = alpha;
        }
        __syncthreads();
        for (int i = tid; i < DOUT * DIN; i += 256) {
            int j = i / DIN, m = i - j * DIN;
            Ws[j * WP + m] *= alphas[j];
        }
        __syncthreads();
    }

    float macc[5][5];
#pragma unroll
    for (int aa = 0; aa < 5; ++aa)
#pragma unroll
        for (int bb = 0; bb < 5; ++bb) macc[aa][bb] = 0.f;
    for (int j = 0; j < DOUT; ++j) {
        float av[5], bv[5];
#pragma unroll
        for (int aa = 0; aa < 5; ++aa) av[aa] = WsA[j * WP + tj + 16 * aa];
#pragma unroll
        for (int bb = 0; bb < 5; ++bb) bv[bb] = WsB[j * WP + tk + 16 * bb];
#pragma unroll
        for (int aa = 0; aa < 5; ++aa)
#pragma unroll
            for (int bb = 0; bb < 5; ++bb) macc[aa][bb] += av[aa] * bv[bb];
    }
    __nv_bfloat16* mh = gMbf[s][0];
    __nv_bfloat16* ml = gMbf[s][1];
#pragma unroll
    for (int aa = 0; aa < 5; ++aa)
#pragma unroll
        for (int bb = 0; bb < 5; ++bb) {
            int p = tj + 16 * aa, q = tk + 16 * bb;
            float m = macc[aa][bb];
            __nv_bfloat16 h = __float2bfloat16(m);
            mh[p * 88 + q] = h;
            ml[p * 88 + q] = __float2bfloat16(m - __bfloat162float(h));
        }
    if (tid < DIN) {
        float u = 0.f;
        for (int j = 0; j < DOUT; ++j) u += WsA[j * WP + tid] * dB[j];
        gU[s * DIN + tid] = u;
    } else if (tid < 2 * DIN) {
        int q = tid - DIN;
        float v = 0.f;
        for (int j = 0; j < DOUT; ++j) v += dA[j] * WsB[j * WP + q];
        gV[s * DIN + q] = v;
    } else if (tid == 2 * DIN) {
        float c = 0.f;
        for (int j = 0; j < DOUT; ++j) c += dA[j] * dB[j];
        gCc[s] = c;
    }
}

// ---------------------------------------------------------------------------
// K4: mma.sync main pass (unchanged from R15). 64 rows/block, 256 thr,
// ~98 KB smem -> 2 blocks/SM.
// ---------------------------------------------------------------------------
#define XPITCH 176
#define XB(t, h) (((t) * 2 + (h)) * 11264)
#define O_M   67584
#define O_US  95744
#define O_VS  96704
#define O_CC  97664
#define O_SIM 97680
#define O_PSM 99216
#define KMAIN_SMEM 99984

__global__ __launch_bounds__(256, 2)
void k_main(const float* __restrict__ X0, const float* __restrict__ X1,
            const float* __restrict__ X2, float* __restrict__ out)
{
    extern __shared__ __align__(16) char smc[];
    float* us   = (float*)(smc + O_US);
    float* vs   = (float*)(smc + O_VS);
    float* ccs  = (float*)(smc + O_CC);
    float* simw = (float*)(smc + O_SIM);
    float* psm  = (float*)(smc + O_PSM);
    const uint32_t sb = smem_u32(smc);
    const int tid = threadIdx.x, wid = tid >> 5, lane = tid & 31;
    const int wm = wid >> 1, wn = wid & 1;
    const long long base = (long long)blockIdx.x * 64;

    const float* Xp[3] = {X0, X1, X2};
    for (int t = 0; t < 3; ++t) {
        const float4* src4 = (const float4*)(Xp[t] + base * DIN);
        char* hi = smc + XB(t, 0);
        char* lo = smc + XB(t, 1);
        for (int i4 = tid; i4 < 64 * 20; i4 += 256) {
            int r = i4 / 20, q0 = 4 * (i4 - r * 20);
            float4 v = src4[i4];
            __nv_bfloat16 h0 = __float2bfloat16(v.x), h1 = __float2bfloat16(v.y);
            __nv_bfloat16 h2 = __float2bfloat16(v.z), h3 = __float2bfloat16(v.w);
            int o = r * XPITCH + q0 * 2;
            __nv_bfloat162 p01(h0, h1), p23(h2, h3);
            *(uint32_t*)(hi + o)     = *(uint32_t*)&p01;
            *(uint32_t*)(hi + o + 4) = *(uint32_t*)&p23;
            *(uint32_t*)(lo + o)     = bfpack(v.x - __bfloat162float(h0),
                                              v.y - __bfloat162float(h1));
            *(uint32_t*)(lo + o + 4) = bfpack(v.z - __bfloat162float(h2),
                                              v.w - __bfloat162float(h3));
        }
    }
    if (tid < 3 * DIN) { us[tid] = gU[tid]; vs[tid] = gV[tid]; }
    if (tid < 3)       ccs[tid] = gCc[tid];
    __syncthreads();

    const int g = lane >> 2, tq = lane & 3;
    const int aln = lane & 15, akoff = (lane < 16) ? 0 : 16;
    const int bln = lane & 7,  bkoff = (lane & 8) ? 16 : 0;

    for (int s = 0; s < 3; ++s) {
        const int aS = (s == 2) ? 1 : 0;
        const int bS = (s == 0) ? 1 : 2;

        const float4* mg = (const float4*)gMbf[s][0];
        for (int i = tid; i < 1760; i += 256) ((float4*)(smc + O_M))[i] = mg[i];
        __syncthreads();

        float d[5][4];
#pragma unroll
        for (int n = 0; n < 5; ++n)
#pragma unroll
            for (int i = 0; i < 4; ++i) d[n][i] = 0.f;

        const uint32_t tA[3] = {sb + XB(bS, 0), sb + XB(bS, 0), sb + XB(bS, 1)};
        const uint32_t tB[3] = {sb + O_M, sb + O_M + 14080, sb + O_M};
#pragma unroll
        for (int term = 0; term < 3; ++term) {
            uint32_t abase = tA[term] + (16 * wm + aln) * XPITCH + akoff;
            uint32_t bbase = tB[term] + (40 * wn + bln) * XPITCH + bkoff;
#pragma unroll
            for (int ks = 0; ks < 5; ++ks) {
                uint32_t a0, a1, a2, a3;
                ldsm4(a0, a1, a2, a3, abase + ks * 32);
#pragma unroll
                for (int n = 0; n < 5; ++n) {
                    uint32_t b0, b1;
                    ldsm2(b0, b1, bbase + n * 8 * XPITCH + ks * 32);
                    mma16816(d[n], a0, a1, a2, a3, b0, b1);
                }
            }
        }

        const char* ah = smc + XB(aS, 0);
        const char* al = smc + XB(aS, 1);
        const char* bh = smc + XB(bS, 0);
        const char* bl = smc + XB(bS, 1);
        const int r0 = 16 * wm + g, r1 = r0 + 8;
        float s0 = 0.f, s1 = 0.f;
#pragma unroll
        for (int n = 0; n < 5; ++n) {
            int p0 = 40 * wn + 8 * n + 2 * tq;
            float2 uu = *(const float2*)&us[s * DIN + p0];
            float2 vv = *(const float2*)&vs[s * DIN + p0];
            float2 xa0 = rd2(ah, al, r0 * XPITCH + p0 * 2);
            float2 xa1 = rd2(ah, al, r1 * XPITCH + p0 * 2);
            float2 xb0 = rd2(bh, bl, r0 * XPITCH + p0 * 2);
            float2 xb1 = rd2(bh, bl, r1 * XPITCH + p0 * 2);
            s0 += (d[n][0] + uu.x) * xa0.x + (d[n][1] + uu.y) * xa0.y
                + vv.x * xb0.x + vv.y * xb0.y;
            s1 += (d[n][2] + uu.x) * xa1.x + (d[n][3] + uu.y) * xa1.y
                + vv.x * xb1.x + vv.y * xb1.y;
        }
        s0 += __shfl_xor_sync(0xffffffff, s0, 1);
        s0 += __shfl_xor_sync(0xffffffff, s0, 2);
        s1 += __shfl_xor_sync(0xffffffff, s1, 1);
        s1 += __shfl_xor_sync(0xffffffff, s1, 2);
        if (tq == 0) {
            simw[(wn * 3 + s) * 64 + r0] = s0;
            simw[(wn * 3 + s) * 64 + r1] = s1;
        }
        __syncthreads();
    }

    if (tid < 64) {
        float s0 = simw[0 * 64 + tid] + simw[(3 + 0) * 64 + tid] + ccs[0];
        float s1 = simw[1 * 64 + tid] + simw[(3 + 1) * 64 + tid] + ccs[1];
        float s2 = simw[2 * 64 + tid] + simw[(3 + 2) * 64 + tid] + ccs[2];
        float m = fmaxf(s0, fmaxf(s1, s2));
        float e0 = __expf(s0 - m), e1 = __expf(s1 - m), e2 = __expf(s2 - m);
        float inv = 1.f / (e0 + e1 + e2);
        psm[tid] = e0 * inv;
        psm[64 + tid] = e1 * inv;
        psm[128 + tid] = e2 * inv;
    }
    __syncthreads();

    const float4* s4 = (const float4*)(X0 + base * DIN);
    const float4* l4 = (const float4*)(X1 + base * DIN);
    const float4* r4 = (const float4*)(X2 + base * DIN);
    float4* d4 = (float4*)(out + base * DIN);
    for (int i4 = tid; i4 < 64 * 20; i4 += 256) {
        int r = i4 / 20;
        float p0 = psm[r], p1 = psm[64 + r], p2 = psm[128 + r];
        float4 a = s4[i4], b = l4[i4], c = r4[i4], o;
        o.x = p0 * b.x + p1 * c.x + p2 * a.x;
        o.y = p0 * b.y + p1 * c.y + p2 * a.y;
        o.z = p0 * b.z + p1 * c.z + p2 * a.z;
        o.w = p0 * b.w + p1 * c.w + p2 * a.w;
        d4[i4] = o;
    }
}

// ---------------------------------------------------------------------------
extern "C" void kernel_launch(void* const* d_in, const int* in_sizes, int n_in,
                              void* d_out, int out_size)
{
    const float* sub   = (const float*)d_in[0];
    const float* left  = (const float*)d_in[1];
    const float* right = (const float*)d_in[2];
    Params P;
    for (int s = 0; s < 3; ++s) {
        P.W[s]  = (const float*)d_in[3 + 4 * s + 0];
        P.b[s]  = (const float*)d_in[3 + 4 * s + 1];
        P.g[s]  = (const float*)d_in[3 + 4 * s + 2];
        P.be[s] = (const float*)d_in[3 + 4 * s + 3];
    }
    cudaFuncSetAttribute(k_prep, cudaFuncAttributeMaxDynamicSharedMemorySize, PREP_SMEM);
    cudaFuncSetAttribute(k_main, cudaFuncAttributeMaxDynamicSharedMemorySize, KMAIN_SMEM);

    k_xtx<<<dim3(P1_BLOCKS, 3), 320>>>(sub, left, right);
    k_reduceC<<<(3 * DIN * DIN + 3 * DIN + 255) / 256, 256>>>();
    k_prep<<<3, 256, PREP_SMEM>>>(P, 1.0f / (float)NROWS);
    k_main<<<NROWS / 64, 256, KMAIN_SMEM>>>(sub, left, right, (float*)d_out);
}

// round 17
// speedup vs baseline: 1.3035x; 1.0800x over previous
#include <cuda_runtime.h>
#include <cuda_bf16.h>
#include <cstdint>

#define DIN 80
#define DOUT 160
#define NROWS 262144
#define EPSV 1e-5f
#define P1_BLOCKS 256

// ---- device scratch --------------------------------------------------------
__device__ float gSpart[3 * P1_BLOCKS * DIN];
__device__ float gS[3 * DIN];
__device__ float gCpart[(size_t)6 * P1_BLOCKS * DIN * DIN];  // [s][E/F][blk]
__device__ float gC[3 * DIN * DIN];
__device__ __align__(16) __nv_bfloat16 gMbf[3][2][80 * 88]; // hi/lo, pitch 88
__device__ float gU[3 * DIN];
__device__ float gV[3 * DIN];
__device__ float gCc[3];

struct Params { const float *W[3], *b[3], *g[3], *be[3]; };

__device__ __forceinline__ uint32_t smem_u32(const void* p) {
    uint32_t a;
    asm("{ .reg .u64 t; cvta.to.shared.u64 t, %1; cvt.u32.u64 %0, t; }"
        : "=r"(a) : "l"(p));
    return a;
}
__device__ __forceinline__ void ldsm4(uint32_t& a0, uint32_t& a1, uint32_t& a2,
                                      uint32_t& a3, uint32_t addr) {
    asm volatile("ldmatrix.sync.aligned.m8n8.x4.shared.b16 {%0,%1,%2,%3}, [%4];"
                 : "=r"(a0), "=r"(a1), "=r"(a2), "=r"(a3) : "r"(addr));
}
__device__ __forceinline__ void ldsm2(uint32_t& b0, uint32_t& b1, uint32_t addr) {
    asm volatile("ldmatrix.sync.aligned.m8n8.x2.shared.b16 {%0,%1}, [%2];"
                 : "=r"(b0), "=r"(b1) : "r"(addr));
}
__device__ __forceinline__ void ldsm4t(uint32_t& a0, uint32_t& a1, uint32_t& a2,
                                       uint32_t& a3, uint32_t addr) {
    asm volatile("ldmatrix.sync.aligned.m8n8.x4.trans.shared.b16 {%0,%1,%2,%3}, [%4];"
                 : "=r"(a0), "=r"(a1), "=r"(a2), "=r"(a3) : "r"(addr));
}
__device__ __forceinline__ void ldsm2t(uint32_t& b0, uint32_t& b1, uint32_t addr) {
    asm volatile("ldmatrix.sync.aligned.m8n8.x2.trans.shared.b16 {%0,%1}, [%2];"
                 : "=r"(b0), "=r"(b1) : "r"(addr));
}
__device__ __forceinline__ void mma16816(float* d, uint32_t a0, uint32_t a1,
                                         uint32_t a2, uint32_t a3,
                                         uint32_t b0, uint32_t b1) {
    asm volatile("mma.sync.aligned.m16n8k16.row.col.f32.bf16.bf16.f32 "
                 "{%0,%1,%2,%3}, {%4,%5,%6,%7}, {%8,%9}, {%0,%1,%2,%3};"
                 : "+f"(d[0]), "+f"(d[1]), "+f"(d[2]), "+f"(d[3])
                 : "r"(a0), "r"(a1), "r"(a2), "r"(a3), "r"(b0), "r"(b1));
}
__device__ __forceinline__ uint32_t bfpack(float a, float b) {
    __nv_bfloat162 t(__float2bfloat16(a), __float2bfloat16(b));
    return *(uint32_t*)&t;
}
__device__ __forceinline__ float2 rd2(const char* hi, const char* lo, int off) {
    __nv_bfloat162 h = *(const __nv_bfloat162*)(hi + off);
    __nv_bfloat162 l = *(const __nv_bfloat162*)(lo + off);
    return make_float2(__bfloat162float(h.x) + __bfloat162float(l.x),
                       __bfloat162float(h.y) + __bfloat162float(l.y));
}

// ---------------------------------------------------------------------------
// K1: X^T X via mma split-2 with symmetry: store E = Xh^T Xh and F = Xh^T Xl
// partials; reduce forms C = E + F + F^T. B frags packed 2-tiles-per-ldsm4t,
// A frag (Xh) hoisted across both terms. X row-major bf16 hi/lo, pitch 176 B.
// ---------------------------------------------------------------------------
#define XP1 176
#define P1T 8

__global__ __launch_bounds__(320)
void k_xtx(const float* __restrict__ X0, const float* __restrict__ X1,
           const float* __restrict__ X2)
{
    __shared__ __align__(16) char XH[128 * XP1];
    __shared__ __align__(16) char XL[128 * XP1];
    __shared__ float psC[16 * 80];

    const int s = blockIdx.y;
    const float* X = (s == 0) ? X0 : (s == 1) ? X1 : X2;
    const int tid = threadIdx.x, wid = tid >> 5, lane = tid & 31;
    const int wm = wid >> 1, wn = wid & 1;
    const uint32_t sh = smem_u32(XH), sl = smem_u32(XL);

    // A (x4.trans) lanes — validated in R16
    const int arow = (lane & 7) + ((lane & 16) ? 8 : 0);
    const int aoff = (lane & 8) ? 16 : 0;
    // B x4.trans: m0,m1 = k-halves of tile 2np; m2,m3 = tile 2np+1
    const int b4row = (lane & 7) + ((lane & 8) ? 8 : 0);
    const int b4col = (lane & 16) ? 16 : 0;
    const int b2row = b4row;                     // x2: lanes 0-15 used
    const int g = lane >> 2, tq = lane & 3;

    float dE[5][4], dF[5][4];
#pragma unroll
    for (int n = 0; n < 5; ++n)
#pragma unroll
        for (int i = 0; i < 4; ++i) { dE[n][i] = 0.f; dF[n][i] = 0.f; }
    float cs4[4] = {0.f, 0.f, 0.f, 0.f};

    const long long rowbase = (long long)blockIdx.x * (P1T * 128);

    for (int t = 0; t < P1T; ++t) {
        const float4* src4 = (const float4*)(X + (rowbase + (long long)t * 128) * DIN);
        for (int i4 = tid; i4 < 128 * 20; i4 += 320) {
            int r = i4 / 20, q0 = 4 * (i4 % 20);
            float4 v = src4[i4];
            __nv_bfloat16 h0 = __float2bfloat16(v.x), h1 = __float2bfloat16(v.y);
            __nv_bfloat16 h2 = __float2bfloat16(v.z), h3 = __float2bfloat16(v.w);
            int o = r * XP1 + q0 * 2;
            __nv_bfloat162 p01(h0, h1), p23(h2, h3);
            *(uint32_t*)(XH + o)     = *(uint32_t*)&p01;
            *(uint32_t*)(XH + o + 4) = *(uint32_t*)&p23;
            *(uint32_t*)(XL + o)     = bfpack(v.x - __bfloat162float(h0),
                                              v.y - __bfloat162float(h1));
            *(uint32_t*)(XL + o + 4) = bfpack(v.z - __bfloat162float(h2),
                                              v.w - __bfloat162float(h3));
            cs4[0] += v.x; cs4[1] += v.y; cs4[2] += v.z; cs4[3] += v.w;
        }
        __syncthreads();

        const uint32_t abase = sh + arow * XP1 + aoff + 32 * wm;
        const uint32_t bcol  = 80 * wn;
#pragma unroll
        for (int ks = 0; ks < 8; ++ks) {
            const uint32_t krow = ks * 16 * XP1;
            uint32_t a0, a1, a2, a3;
            ldsm4t(a0, a1, a2, a3, abase + krow);
            // B from Xh (term E)
            uint32_t bh[10];
            ldsm4t(bh[0], bh[1], bh[2], bh[3],
                   sh + (b4row)*XP1 + krow + bcol + 0 + b4col);
            ldsm4t(bh[4], bh[5], bh[6], bh[7],
                   sh + (b4row)*XP1 + krow + bcol + 32 + b4col);
            ldsm2t(bh[8], bh[9], sh + (b2row)*XP1 + krow + bcol + 64);
            // B from Xl (term F)
            uint32_t bl[10];
            ldsm4t(bl[0], bl[1], bl[2], bl[3],
                   sl + (b4row)*XP1 + krow + bcol + 0 + b4col);
            ldsm4t(bl[4], bl[5], bl[6], bl[7],
                   sl + (b4row)*XP1 + krow + bcol + 32 + b4col);
            ldsm2t(bl[8], bl[9], sl + (b2row)*XP1 + krow + bcol + 64);
#pragma unroll
            for (int n = 0; n < 5; ++n) {
                mma16816(dE[n], a0, a1, a2, a3, bh[2 * n], bh[2 * n + 1]);
                mma16816(dF[n], a0, a1, a2, a3, bl[2 * n], bl[2 * n + 1]);
            }
        }
        __syncthreads();
    }

    float* dstE = gCpart + ((size_t)(s * 2 + 0) * P1_BLOCKS + blockIdx.x) * (DIN * DIN);
    float* dstF = gCpart + ((size_t)(s * 2 + 1) * P1_BLOCKS + blockIdx.x) * (DIN * DIN);
    const int r0 = 16 * wm + g, r1 = r0 + 8;
#pragma unroll
    for (int n = 0; n < 5; ++n) {
        int c = 40 * wn + 8 * n + 2 * tq;
        dstE[r0 * DIN + c]     = dE[n][0];
        dstE[r0 * DIN + c + 1] = dE[n][1];
        dstE[r1 * DIN + c]     = dE[n][2];
        dstE[r1 * DIN + c + 1] = dE[n][3];
        dstF[r0 * DIN + c]     = dF[n][0];
        dstF[r0 * DIN + c + 1] = dF[n][1];
        dstF[r1 * DIN + c]     = dF[n][2];
        dstF[r1 * DIN + c + 1] = dF[n][3];
    }
#pragma unroll
    for (int j = 0; j < 4; ++j) psC[(tid / 20) * 80 + 4 * (tid % 20) + j] = cs4[j];
    __syncthreads();
    if (tid < DIN) {
        float acc = 0.f;
#pragma unroll
        for (int gg = 0; gg < 16; ++gg) acc += psC[gg * 80 + tid];
        gSpart[(s * P1_BLOCKS + blockIdx.x) * DIN + tid] = acc;
    }
}

// ---------------------------------------------------------------------------
// K2: C = sum_b (E + F) + (sum_b F)^T ; plus column sums.
// ---------------------------------------------------------------------------
__global__ void k_reduceC()
{
    int e = blockIdx.x * blockDim.x + threadIdx.x;
    if (e < 3 * DIN * DIN) {
        int s = e / (DIN * DIN), rem = e - s * (DIN * DIN);
        int j = rem / DIN, k = rem - j * DIN;
        const float* bE  = gCpart + (size_t)(s * 2 + 0) * P1_BLOCKS * (DIN * DIN) + rem;
        const float* bF  = gCpart + (size_t)(s * 2 + 1) * P1_BLOCKS * (DIN * DIN) + rem;
        const float* bFT = gCpart + (size_t)(s * 2 + 1) * P1_BLOCKS * (DIN * DIN)
                         + (k * DIN + j);
        float acc = 0.f;
#pragma unroll 4
        for (int b = 0; b < P1_BLOCKS; ++b) {
            size_t o = (size_t)b * (DIN * DIN);
            acc += bE[o] + bF[o] + bFT[o];
        }
        gC[e] = acc;
    } else if (e < 3 * DIN * DIN + 3 * DIN) {
        int h = e - 3 * DIN * DIN, s = h / DIN, k = h - s * DIN;
        float acc = 0.f;
#pragma unroll 8
        for (int b = 0; b < P1_BLOCKS; ++b) acc += gSpart[(s * P1_BLOCKS + b) * DIN + k];
        gS[s * DIN + k] = acc;
    }
}

// ---------------------------------------------------------------------------
// K3: fused stats + build M (split-2 bf16, [p][q] pitch 88), u, v, c.
// ---------------------------------------------------------------------------
#define WP 84
#define TPP (DOUT + 8)
#define PREP_SMEM ((2*DOUT*WP + DIN*DIN + 16*TPP + DOUT + DIN + 2*DOUT) * 4)

__global__ __launch_bounds__(256)
void k_prep(Params P, float invN)
{
    extern __shared__ __align__(16) float sp[];
    float* WsA = sp;
    float* WsB = WsA + DOUT * WP;
    float* Cs  = WsB + DOUT * WP;
    float* Tp  = Cs + DIN * DIN;
    float* alphas = Tp + 16 * TPP;
    float* xbs = alphas + DOUT;
    float* dA  = xbs + DIN;
    float* dB  = dA + DOUT;

    const int s = blockIdx.x;
    const int a_idx = (s == 2) ? 1 : 0;
    const int b_idx = (s == 0) ? 1 : 2;
    const int tid = threadIdx.x, tj = tid & 15, tk = tid >> 4;

    for (int ph = 0; ph < 2; ++ph) {
        const int t = ph ? b_idx : a_idx;
        float* Ws = ph ? WsB : WsA;
        float* dd = ph ? dB : dA;
        const float4* Wg4 = (const float4*)P.W[t];
        for (int i4 = tid; i4 < DOUT * 20; i4 += 256) {
            int j = i4 / 20, k4 = i4 - j * 20;
            *(float4*)&Ws[j * WP + 4 * k4] = Wg4[i4];
        }
        const float4* Cg4 = (const float4*)&gC[t * DIN * DIN];
        for (int i4 = tid; i4 < (DIN * DIN) / 4; i4 += 256) ((float4*)Cs)[i4] = Cg4[i4];
        if (tid < DIN) xbs[tid] = gS[t * DIN + tid] * invN;
        __syncthreads();

        float acc[10][5];
#pragma unroll
        for (int aa = 0; aa < 10; ++aa)
#pragma unroll
            for (int bb = 0; bb < 5; ++bb) acc[aa][bb] = 0.f;
        for (int m = 0; m < DIN; ++m) {
            float wv[10], cv[5];
#pragma unroll
            for (int aa = 0; aa < 10; ++aa) wv[aa] = Ws[(tj + 16 * aa) * WP + m];
#pragma unroll
            for (int bb = 0; bb < 5; ++bb) cv[bb] = Cs[m * DIN + tk + 16 * bb];
#pragma unroll
            for (int aa = 0; aa < 10; ++aa)
#pragma unroll
                for (int bb = 0; bb < 5; ++bb) acc[aa][bb] += wv[aa] * cv[bb];
        }
#pragma unroll
        for (int aa = 0; aa < 10; ++aa) {
            float ps = 0.f;
#pragma unroll
            for (int bb = 0; bb < 5; ++bb)
                ps += acc[aa][bb] * Ws[(tj + 16 * aa) * WP + tk + 16 * bb];
            Tp[tk * TPP + tj + 16 * aa] = ps;
        }
        __syncthreads();
        if (tid < DOUT) {
            float q = 0.f;
#pragma unroll
            for (int g = 0; g < 16; ++g) q += Tp[g * TPP + tid];
            float wx = 0.f;
#pragma unroll 8
            for (int m = 0; m < DIN; ++m) wx += Ws[tid * WP + m] * xbs[m];
            float bj = P.b[t][tid], mu = wx + bj;
            float var = q * invN - wx * wx;
            float alpha = P.g[t][tid] * rsqrtf(var + EPSV);
            dd[tid] = alpha * bj + (P.be[t][tid] - mu * alpha);
            alphas[tid] = alpha;
        }
        __syncthreads();
        for (int i = tid; i < DOUT * DIN; i += 256) {
            int j = i / DIN, m = i - j * DIN;
            Ws[j * WP + m] *= alphas[j];
        }
        __syncthreads();
    }

    float macc[5][5];
#pragma unroll
    for (int aa = 0; aa < 5; ++aa)
#pragma unroll
        for (int bb = 0; bb < 5; ++bb) macc[aa][bb] = 0.f;
    for (int j = 0; j < DOUT; ++j) {
        float av[5], bv[5];
#pragma unroll
        for (int aa = 0; aa < 5; ++aa) av[aa] = WsA[j * WP + tj + 16 * aa];
#pragma unroll
        for (int bb = 0; bb < 5; ++bb) bv[bb] = WsB[j * WP + tk + 16 * bb];
#pragma unroll
        for (int aa = 0; aa < 5; ++aa)
#pragma unroll
            for (int bb = 0; bb < 5; ++bb) macc[aa][bb] += av[aa] * bv[bb];
    }
    __nv_bfloat16* mh = gMbf[s][0];
    __nv_bfloat16* ml = gMbf[s][1];
#pragma unroll
    for (int aa = 0; aa < 5; ++aa)
#pragma unroll
        for (int bb = 0; bb < 5; ++bb) {
            int p = tj + 16 * aa, q = tk + 16 * bb;
            float m = macc[aa][bb];
            __nv_bfloat16 h = __float2bfloat16(m);
            mh[p * 88 + q] = h;
            ml[p * 88 + q] = __float2bfloat16(m - __bfloat162float(h));
        }
    if (tid < DIN) {
        float u = 0.f;
        for (int j = 0; j < DOUT; ++j) u += WsA[j * WP + tid] * dB[j];
        gU[s * DIN + tid] = u;
    } else if (tid < 2 * DIN) {
        int q = tid - DIN;
        float v = 0.f;
        for (int j = 0; j < DOUT; ++j) v += dA[j] * WsB[j * WP + q];
        gV[s * DIN + q] = v;
    } else if (tid == 2 * DIN) {
        float c = 0.f;
        for (int j = 0; j < DOUT; ++j) c += dA[j] * dB[j];
        gCc[s] = c;
    }
}

// ---------------------------------------------------------------------------
// K4: mma main pass. 64 rows/block, 256 thr, 2 blocks/SM. B frags packed
// 2-tiles-per-ldsm4; A (xh,xl) and B (Mh,Ml) frags hoisted across the 3
// split terms: per ks 8 ldsm + 15 mma (was 20 ldsm).
// ---------------------------------------------------------------------------
#define XPITCH 176
#define XB(t, h) (((t) * 2 + (h)) * 11264)
#define O_M   67584
#define O_US  95744
#define O_VS  96704
#define O_CC  97664
#define O_SIM 97680
#define O_PSM 99216
#define KMAIN_SMEM 99984

__global__ __launch_bounds__(256, 2)
void k_main(const float* __restrict__ X0, const float* __restrict__ X1,
            const float* __restrict__ X2, float* __restrict__ out)
{
    extern __shared__ __align__(16) char smc[];
    float* us   = (float*)(smc + O_US);
    float* vs   = (float*)(smc + O_VS);
    float* ccs  = (float*)(smc + O_CC);
    float* simw = (float*)(smc + O_SIM);
    float* psm  = (float*)(smc + O_PSM);
    const uint32_t sb = smem_u32(smc);
    const int tid = threadIdx.x, wid = tid >> 5, lane = tid & 31;
    const int wm = wid >> 1, wn = wid & 1;
    const long long base = (long long)blockIdx.x * 64;

    const float* Xp[3] = {X0, X1, X2};
    for (int t = 0; t < 3; ++t) {
        const float4* src4 = (const float4*)(Xp[t] + base * DIN);
        char* hi = smc + XB(t, 0);
        char* lo = smc + XB(t, 1);
        for (int i4 = tid; i4 < 64 * 20; i4 += 256) {
            int r = i4 / 20, q0 = 4 * (i4 - r * 20);
            float4 v = src4[i4];
            __nv_bfloat16 h0 = __float2bfloat16(v.x), h1 = __float2bfloat16(v.y);
            __nv_bfloat16 h2 = __float2bfloat16(v.z), h3 = __float2bfloat16(v.w);
            int o = r * XPITCH + q0 * 2;
            __nv_bfloat162 p01(h0, h1), p23(h2, h3);
            *(uint32_t*)(hi + o)     = *(uint32_t*)&p01;
            *(uint32_t*)(hi + o + 4) = *(uint32_t*)&p23;
            *(uint32_t*)(lo + o)     = bfpack(v.x - __bfloat162float(h0),
                                              v.y - __bfloat162float(h1));
            *(uint32_t*)(lo + o + 4) = bfpack(v.z - __bfloat162float(h2),
                                              v.w - __bfloat162float(h3));
        }
    }
    if (tid < 3 * DIN) { us[tid] = gU[tid]; vs[tid] = gV[tid]; }
    if (tid < 3)       ccs[tid] = gCc[tid];
    __syncthreads();

    const int g = lane >> 2, tq = lane & 3;
    const int aln = lane & 15, akoff = (lane < 16) ? 0 : 16;
    // B x4 (non-trans): m0,m1 = k-halves of tile 2np; m2,m3 = tile 2np+1
    const int b4r = (lane & 7) + ((lane & 16) ? 8 : 0);
    const int b4k = (lane & 8) ? 16 : 0;

    for (int s = 0; s < 3; ++s) {
        const int aS = (s == 2) ? 1 : 0;
        const int bS = (s == 0) ? 1 : 2;

        const float4* mg = (const float4*)gMbf[s][0];
        for (int i = tid; i < 1760; i += 256) ((float4*)(smc + O_M))[i] = mg[i];
        __syncthreads();

        float d[5][4];
#pragma unroll
        for (int n = 0; n < 5; ++n)
#pragma unroll
            for (int i = 0; i < 4; ++i) d[n][i] = 0.f;

        const uint32_t ah_base = sb + XB(bS, 0) + (16 * wm + aln) * XPITCH + akoff;
        const uint32_t al_base = sb + XB(bS, 1) + (16 * wm + aln) * XPITCH + akoff;
        const uint32_t mh_base = sb + O_M;
        const uint32_t ml_base = sb + O_M + 14080;
#pragma unroll
        for (int ks = 0; ks < 5; ++ks) {
            const uint32_t ko = ks * 32;
            uint32_t ah0, ah1, ah2, ah3, al0, al1, al2, al3;
            ldsm4(ah0, ah1, ah2, ah3, ah_base + ko);
            ldsm4(al0, al1, al2, al3, al_base + ko);
            uint32_t bh[10], bl[10];
            ldsm4(bh[0], bh[1], bh[2], bh[3],
                  mh_base + (40 * wn + 0 + b4r) * XPITCH + b4k + ko);
            ldsm4(bh[4], bh[5], bh[6], bh[7],
                  mh_base + (40 * wn + 16 + b4r) * XPITCH + b4k + ko);
            ldsm2(bh[8], bh[9],
                  mh_base + (40 * wn + 32 + (lane & 7)) * XPITCH + b4k + ko);
            ldsm4(bl[0], bl[1], bl[2], bl[3],
                  ml_base + (40 * wn + 0 + b4r) * XPITCH + b4k + ko);
            ldsm4(bl[4], bl[5], bl[6], bl[7],
                  ml_base + (40 * wn + 16 + b4r) * XPITCH + b4k + ko);
            ldsm2(bl[8], bl[9],
                  ml_base + (40 * wn + 32 + (lane & 7)) * XPITCH + b4k + ko);
#pragma unroll
            for (int n = 0; n < 5; ++n) {
                mma16816(d[n], ah0, ah1, ah2, ah3, bh[2 * n], bh[2 * n + 1]); // Mh.xh
                mma16816(d[n], ah0, ah1, ah2, ah3, bl[2 * n], bl[2 * n + 1]); // Ml.xh
                mma16816(d[n], al0, al1, al2, al3, bh[2 * n], bh[2 * n + 1]); // Mh.xl
            }
        }

        const char* ah = smc + XB(aS, 0);
        const char* al = smc + XB(aS, 1);
        const char* bh2 = smc + XB(bS, 0);
        const char* bl2 = smc + XB(bS, 1);
        const int r0 = 16 * wm + g, r1 = r0 + 8;
        float s0 = 0.f, s1 = 0.f;
#pragma unroll
        for (int n = 0; n < 5; ++n) {
            int p0 = 40 * wn + 8 * n + 2 * tq;
            float2 uu = *(const float2*)&us[s * DIN + p0];
            float2 vv = *(const float2*)&vs[s * DIN + p0];
            float2 xa0 = rd2(ah, al, r0 * XPITCH + p0 * 2);
            float2 xa1 = rd2(ah, al, r1 * XPITCH + p0 * 2);
            float2 xb0 = rd2(bh2, bl2, r0 * XPITCH + p0 * 2);
            float2 xb1 = rd2(bh2, bl2, r1 * XPITCH + p0 * 2);
            s0 += (d[n][0] + uu.x) * xa0.x + (d[n][1] + uu.y) * xa0.y
                + vv.x * xb0.x + vv.y * xb0.y;
            s1 += (d[n][2] + uu.x) * xa1.x + (d[n][3] + uu.y) * xa1.y
                + vv.x * xb1.x + vv.y * xb1.y;
        }
        s0 += __shfl_xor_sync(0xffffffff, s0, 1);
        s0 += __shfl_xor_sync(0xffffffff, s0, 2);
        s1 += __shfl_xor_sync(0xffffffff, s1, 1);
        s1 += __shfl_xor_sync(0xffffffff, s1, 2);
        if (tq == 0) {
            simw[(wn * 3 + s) * 64 + r0] = s0;
            simw[(wn * 3 + s) * 64 + r1] = s1;
        }
        __syncthreads();
    }

    if (tid < 64) {
        float s0 = simw[0 * 64 + tid] + simw[(3 + 0) * 64 + tid] + ccs[0];
        float s1 = simw[1 * 64 + tid] + simw[(3 + 1) * 64 + tid] + ccs[1];
        float s2 = simw[2 * 64 + tid] + simw[(3 + 2) * 64 + tid] + ccs[2];
        float m = fmaxf(s0, fmaxf(s1, s2));
        float e0 = __expf(s0 - m), e1 = __expf(s1 - m), e2 = __expf(s2 - m);
        float inv = 1.f / (e0 + e1 + e2);
        psm[tid] = e0 * inv;
        psm[64 + tid] = e1 * inv;
        psm[128 + tid] = e2 * inv;
    }
    __syncthreads();

    const float4* s4 = (const float4*)(X0 + base * DIN);
    const float4* l4 = (const float4*)(X1 + base * DIN);
    const float4* r4 = (const float4*)(X2 + base * DIN);
    float4* d4 = (float4*)(out + base * DIN);
    for (int i4 = tid; i4 < 64 * 20; i4 += 256) {
        int r = i4 / 20;
        float p0 = psm[r], p1 = psm[64 + r], p2 = psm[128 + r];
        float4 a = s4[i4], b = l4[i4], c = r4[i4], o;
        o.x = p0 * b.x + p1 * c.x + p2 * a.x;
        o.y = p0 * b.y + p1 * c.y + p2 * a.y;
        o.z = p0 * b.z + p1 * c.z + p2 * a.z;
        o.w = p0 * b.w + p1 * c.w + p2 * a.w;
        d4[i4] = o;
    }
}

// ---------------------------------------------------------------------------
extern "C" void kernel_launch(void* const* d_in, const int* in_sizes, int n_in,
                              void* d_out, int out_size)
{
    const float* sub   = (const float*)d_in[0];
    const float* left  = (const float*)d_in[1];
    const float* right = (const float*)d_in[2];
    Params P;
    for (int s = 0; s < 3; ++s) {
        P.W[s]  = (const float*)d_in[3 + 4 * s + 0];
        P.b[s]  = (const float*)d_in[3 + 4 * s + 1];
        P.g[s]  = (const float*)d_in[3 + 4 * s + 2];
        P.be[s] = (const float*)d_in[3 + 4 * s + 3];
    }
    cudaFuncSetAttribute(k_prep, cudaFuncAttributeMaxDynamicSharedMemorySize, PREP_SMEM);
    cudaFuncSetAttribute(k_main, cudaFuncAttributeMaxDynamicSharedMemorySize, KMAIN_SMEM);

    k_xtx<<<dim3(P1_BLOCKS, 3), 320>>>(sub, left, right);
    k_reduceC<<<(3 * DIN * DIN + 3 * DIN + 255) / 256, 256>>>();
    k_prep<<<3, 256, PREP_SMEM>>>(P, 1.0f / (float)NROWS);
    k_main<<<NROWS / 64, 256, KMAIN_SMEM>>>(sub, left, right, (float*)d_out);
}